// round 2
// baseline (speedup 1.0000x reference)
#include <cuda_runtime.h>
#include <math.h>

#define HID 256
#define NF  64

// Precomputed Gram matrix G = feature_emb @ feature_emb.T  (64x64)
__device__ float d_G[NF * NF];

__global__ void compute_G_kernel(const float* __restrict__ fe) {
    int i = blockIdx.x, j = threadIdx.x;
    const float4* a = (const float4*)(fe + i * HID);
    const float4* b = (const float4*)(fe + j * HID);
    float s = 0.f;
#pragma unroll 8
    for (int k = 0; k < HID / 4; k++) {
        float4 x = a[k], y = b[k];
        s = fmaf(x.x, y.x, fmaf(x.y, y.y, fmaf(x.z, y.z, fmaf(x.w, y.w, s))));
    }
    d_G[i * NF + j] = s;
}

// ---- packed f32x2 helpers ----
__device__ __forceinline__ unsigned long long pk2(float lo, float hi) {
    unsigned long long r;
    asm("mov.b64 %0,{%1,%2};" : "=l"(r) : "f"(lo), "f"(hi));
    return r;
}
__device__ __forceinline__ void up2(unsigned long long v, float& lo, float& hi) {
    asm("mov.b64 {%0,%1},%2;" : "=f"(lo), "=f"(hi) : "l"(v));
}
__device__ __forceinline__ void fma2(unsigned long long& d, unsigned long long a,
                                     unsigned long long b) {
    asm("fma.rn.f32x2 %0,%1,%2,%0;" : "+l"(d) : "l"(a), "l"(b));
}
__device__ __forceinline__ float gelu_exact(float x) {
    return 0.5f * x * (1.f + erff(x * 0.7071067811865476f));
}

#define R 8  // rows (edges) per warp

// acc = A(R rows from smem, K cols, row stride ASTRIDE) @ W (K x 256)
// acc[r][0..1] -> cols [c0..c0+3], acc[r][2..3] -> cols [c0+128..c0+131]
// Weights loaded as ulonglong2: LDG.128 register pair IS the packed f32x2 operand.
template <int K, int ASTRIDE>
__device__ __forceinline__ void gemm_n256(const float* __restrict__ W, const float* As,
                                          int lane, unsigned long long acc[R][4]) {
    const int c0 = lane * 4;
#pragma unroll 1
    for (int k = 0; k < K; k += 4) {
        float4 a4[R];
#pragma unroll
        for (int r = 0; r < R; r++) a4[r] = *(const float4*)(As + r * ASTRIDE + k);
#pragma unroll
        for (int kk = 0; kk < 4; kk++) {
            ulonglong2 wlo = *(const ulonglong2*)(W + (k + kk) * 256 + c0);
            ulonglong2 whi = *(const ulonglong2*)(W + (k + kk) * 256 + c0 + 128);
#pragma unroll
            for (int r = 0; r < R; r++) {
                float av = ((const float*)&a4[r])[kk];
                unsigned long long aa = pk2(av, av);
                fma2(acc[r][0], aa, wlo.x);
                fma2(acc[r][1], aa, wlo.y);
                fma2(acc[r][2], aa, whi.x);
                fma2(acc[r][3], aa, whi.y);
            }
        }
    }
}

extern "C" __global__ void __launch_bounds__(128, 2)
arn_fused(const float* __restrict__ known_mask, const int* __restrict__ obs_idx,
          const int* __restrict__ obs_mask_idx, const int* __restrict__ attr_idx,
          const float* __restrict__ obs_embs,
          const float* __restrict__ rm_W1, const float* __restrict__ rm_b1,
          const float* __restrict__ rm_W2, const float* __restrict__ rm_b2,
          const float* __restrict__ rr_W, const float* __restrict__ rr_b,
          const float* __restrict__ rc_W, const float* __restrict__ rc_b,
          float* __restrict__ out, int E) {
    // per-warp private slices: warp w owns rows [R*w, R*w+R)
    __shared__ float sm_f[32 * NF];   // softmax(m) (A/B), then x (C/D)
    __shared__ float sm_h[32 * HID];  // h1 (B->C), then y (D->E)

    const int w = threadIdx.x >> 5;
    const int lane = threadIdx.x & 31;
    const int row0 = w * R;
    const long base = (long)blockIdx.x * 32 + row0;
    const int c0 = lane * 4;

    int oiv[R], atv[R], omiv[R];
    bool valid[R];
#pragma unroll
    for (int r = 0; r < R; r++) {
        long e = base + r;
        valid[r] = (e < E);
        long ec = valid[r] ? e : (long)(E - 1);
        oiv[r] = obs_idx[ec];
        omiv[r] = obs_mask_idx[ec];
        atv[r] = attr_idx[ec];
    }

    // ---- Phase A: m = softmax(known_mask[omi] * (1 - e_attr)) over F=64 ----
#pragma unroll
    for (int r = 0; r < R; r++) {
        const float* km = known_mask + (long)omiv[r] * NF;
        float v0 = km[lane];
        float v1 = km[lane + 32];
        if (lane == atv[r]) v0 = 0.f;
        if (lane + 32 == atv[r]) v1 = 0.f;
        float mx = fmaxf(v0, v1);
#pragma unroll
        for (int o = 16; o > 0; o >>= 1) mx = fmaxf(mx, __shfl_xor_sync(0xffffffffu, mx, o));
        float e0 = expf(v0 - mx), e1 = expf(v1 - mx);
        float s = e0 + e1;
#pragma unroll
        for (int o = 16; o > 0; o >>= 1) s += __shfl_xor_sync(0xffffffffu, s, o);
        float inv = 1.f / s;
        sm_f[(row0 + r) * NF + lane] = e0 * inv;
        sm_f[(row0 + r) * NF + lane + 32] = e1 * inv;
    }
    __syncwarp();

    // ---- Phase B: h1 = gelu(m @ rm_W1 + rm_b1)   [R x 256], K=64 ----
    {
        unsigned long long acc[R][4] = {};
        gemm_n256<NF, NF>(rm_W1, sm_f + row0 * NF, lane, acc);
        float4 bA = *(const float4*)(rm_b1 + c0);
        float4 bB = *(const float4*)(rm_b1 + c0 + 128);
#pragma unroll
        for (int r = 0; r < R; r++) {
            float v[8];
            up2(acc[r][0], v[0], v[1]);
            up2(acc[r][1], v[2], v[3]);
            up2(acc[r][2], v[4], v[5]);
            up2(acc[r][3], v[6], v[7]);
            float4 oA, oB;
            oA.x = gelu_exact(v[0] + bA.x);
            oA.y = gelu_exact(v[1] + bA.y);
            oA.z = gelu_exact(v[2] + bA.z);
            oA.w = gelu_exact(v[3] + bA.w);
            oB.x = gelu_exact(v[4] + bB.x);
            oB.y = gelu_exact(v[5] + bB.y);
            oB.z = gelu_exact(v[6] + bB.z);
            oB.w = gelu_exact(v[7] + bB.w);
            *(float4*)(sm_h + (row0 + r) * HID + c0) = oA;
            *(float4*)(sm_h + (row0 + r) * HID + c0 + 128) = oB;
        }
    }
    __syncwarp();

    // ---- Phase C: mJ = gelu(h1 @ rm_W2 + rm_b2); x = G[attr] * mJ  [R x 64], K=256 ----
    {
        unsigned long long accC[R] = {};
        const int cc = lane * 2;
#pragma unroll 1
        for (int k = 0; k < HID; k += 4) {
            float4 a4[R];
#pragma unroll
            for (int r = 0; r < R; r++) a4[r] = *(const float4*)(sm_h + (row0 + r) * HID + k);
#pragma unroll
            for (int kk = 0; kk < 4; kk++) {
                unsigned long long wp = *(const unsigned long long*)(rm_W2 + (k + kk) * NF + cc);
#pragma unroll
                for (int r = 0; r < R; r++) {
                    float av = ((const float*)&a4[r])[kk];
                    fma2(accC[r], pk2(av, av), wp);
                }
            }
        }
        float2 b2v = *(const float2*)(rm_b2 + cc);
#pragma unroll
        for (int r = 0; r < R; r++) {
            float x0, x1;
            up2(accC[r], x0, x1);
            x0 = gelu_exact(x0 + b2v.x);
            x1 = gelu_exact(x1 + b2v.y);
            float2 g = *(const float2*)(d_G + atv[r] * NF + cc);
            sm_f[(row0 + r) * NF + cc] = x0 * g.x;
            sm_f[(row0 + r) * NF + cc + 1] = x1 * g.y;
        }
    }
    __syncwarp();

    // ---- Phase D: a = gelu(x @ rr_W + rr_b); y = obs_h * a  [R x 256], K=64 ----
    {
        unsigned long long acc[R][4] = {};
        gemm_n256<NF, NF>(rr_W, sm_f + row0 * NF, lane, acc);
        float4 bA = *(const float4*)(rr_b + c0);
        float4 bB = *(const float4*)(rr_b + c0 + 128);
#pragma unroll
        for (int r = 0; r < R; r++) {
            float v[8];
            up2(acc[r][0], v[0], v[1]);
            up2(acc[r][1], v[2], v[3]);
            up2(acc[r][2], v[4], v[5]);
            up2(acc[r][3], v[6], v[7]);
            float4 hA = *(const float4*)(obs_embs + (long)oiv[r] * HID + c0);
            float4 hB = *(const float4*)(obs_embs + (long)oiv[r] * HID + c0 + 128);
            float4 oA, oB;
            oA.x = gelu_exact(v[0] + bA.x) * hA.x;
            oA.y = gelu_exact(v[1] + bA.y) * hA.y;
            oA.z = gelu_exact(v[2] + bA.z) * hA.z;
            oA.w = gelu_exact(v[3] + bA.w) * hA.w;
            oB.x = gelu_exact(v[4] + bB.x) * hB.x;
            oB.y = gelu_exact(v[5] + bB.y) * hB.y;
            oB.z = gelu_exact(v[6] + bB.z) * hB.z;
            oB.w = gelu_exact(v[7] + bB.w) * hB.w;
            *(float4*)(sm_h + (row0 + r) * HID + c0) = oA;
            *(float4*)(sm_h + (row0 + r) * HID + c0 + 128) = oB;
        }
    }
    __syncwarp();

    // ---- Phase E: out = gelu(y @ rc_W + rc_b)  [R x 256], K=256 ----
    {
        unsigned long long acc[R][4] = {};
        gemm_n256<HID, HID>(rc_W, sm_h + row0 * HID, lane, acc);
        float4 bA = *(const float4*)(rc_b + c0);
        float4 bB = *(const float4*)(rc_b + c0 + 128);
#pragma unroll
        for (int r = 0; r < R; r++) {
            if (!valid[r]) continue;
            float v[8];
            up2(acc[r][0], v[0], v[1]);
            up2(acc[r][1], v[2], v[3]);
            up2(acc[r][2], v[4], v[5]);
            up2(acc[r][3], v[6], v[7]);
            float4 oA, oB;
            oA.x = gelu_exact(v[0] + bA.x);
            oA.y = gelu_exact(v[1] + bA.y);
            oA.z = gelu_exact(v[2] + bA.z);
            oA.w = gelu_exact(v[3] + bA.w);
            oB.x = gelu_exact(v[4] + bB.x);
            oB.y = gelu_exact(v[5] + bB.y);
            oB.z = gelu_exact(v[6] + bB.z);
            oB.w = gelu_exact(v[7] + bB.w);
            *(float4*)(out + (base + r) * HID + c0) = oA;
            *(float4*)(out + (base + r) * HID + c0 + 128) = oB;
        }
    }
}

extern "C" void kernel_launch(void* const* d_in, const int* in_sizes, int n_in,
                              void* d_out, int out_size) {
    const float* known_mask = (const float*)d_in[0];
    const int* obs_idx = (const int*)d_in[1];
    const int* obs_mask_idx = (const int*)d_in[2];
    const int* attr_idx = (const int*)d_in[3];
    const float* obs_embs = (const float*)d_in[4];
    const float* feature_emb = (const float*)d_in[5];
    const float* rm_W1 = (const float*)d_in[6];
    const float* rm_b1 = (const float*)d_in[7];
    const float* rm_W2 = (const float*)d_in[8];
    const float* rm_b2 = (const float*)d_in[9];
    const float* rr_W = (const float*)d_in[10];
    const float* rr_b = (const float*)d_in[11];
    const float* rc_W = (const float*)d_in[12];
    const float* rc_b = (const float*)d_in[13];
    int E = in_sizes[1];

    compute_G_kernel<<<NF, NF>>>(feature_emb);
    int grid = (E + 31) / 32;  // 32 rows per block (4 warps x 8 rows)
    arn_fused<<<grid, 128>>>(known_mask, obs_idx, obs_mask_idx, attr_idx, obs_embs,
                             rm_W1, rm_b1, rm_W2, rm_b2, rr_W, rr_b, rc_W, rc_b,
                             (float*)d_out, E);
}

// round 4
// speedup vs baseline: 1.4581x; 1.4581x over previous
#include <cuda_runtime.h>
#include <cuda_bf16.h>
#include <math.h>

#define HID 256
#define NF  64
#define YS  264   // padded bf16 row stride (conflict-free a-frag LDS)

// ---------------- device scratch ----------------
__device__ float d_G[NF * NF];
__device__ uint2 d_Wfh[16 * 32 * 32];  // rc_W bf16-hi fragments [ks][nt][lane]
__device__ uint2 d_Wfl[16 * 32 * 32];  // bf16-lo fragments

// ---------------- helpers ----------------
__device__ __forceinline__ unsigned long long pk2(float lo, float hi) {
    unsigned long long r;
    asm("mov.b64 %0,{%1,%2};" : "=l"(r) : "f"(lo), "f"(hi));
    return r;
}
__device__ __forceinline__ void up2(unsigned long long v, float& lo, float& hi) {
    asm("mov.b64 {%0,%1},%2;" : "=f"(lo), "=f"(hi) : "l"(v));
}
__device__ __forceinline__ void fma2(unsigned long long& d, unsigned long long a,
                                     unsigned long long b) {
    asm("fma.rn.f32x2 %0,%1,%2,%0;" : "+l"(d) : "l"(a), "l"(b));
}
__device__ __forceinline__ float gelu_exact(float x) {
    return 0.5f * x * (1.f + erff(x * 0.7071067811865476f));
}
__device__ __forceinline__ unsigned pack_bf(__nv_bfloat16 a, __nv_bfloat16 b) {
    return (unsigned)__bfloat16_as_ushort(a) | ((unsigned)__bfloat16_as_ushort(b) << 16);
}
__device__ __forceinline__ void split4(float4 v, uint2& ph, uint2& pl) {
    __nv_bfloat16 h0 = __float2bfloat16(v.x), h1 = __float2bfloat16(v.y);
    __nv_bfloat16 h2 = __float2bfloat16(v.z), h3 = __float2bfloat16(v.w);
    __nv_bfloat16 l0 = __float2bfloat16(v.x - __bfloat162float(h0));
    __nv_bfloat16 l1 = __float2bfloat16(v.y - __bfloat162float(h1));
    __nv_bfloat16 l2 = __float2bfloat16(v.z - __bfloat162float(h2));
    __nv_bfloat16 l3 = __float2bfloat16(v.w - __bfloat162float(h3));
    ph.x = pack_bf(h0, h1);
    ph.y = pack_bf(h2, h3);
    pl.x = pack_bf(l0, l1);
    pl.y = pack_bf(l2, l3);
}
__device__ __forceinline__ void mma_bf16(float c[4], unsigned a0, unsigned a1, unsigned a2,
                                         unsigned a3, unsigned b0, unsigned b1) {
    asm("mma.sync.aligned.m16n8k16.row.col.f32.bf16.bf16.f32 "
        "{%0,%1,%2,%3},{%4,%5,%6,%7},{%8,%9},{%0,%1,%2,%3};"
        : "+f"(c[0]), "+f"(c[1]), "+f"(c[2]), "+f"(c[3])
        : "r"(a0), "r"(a1), "r"(a2), "r"(a3), "r"(b0), "r"(b1));
}

// ---------------- prep kernels ----------------
__global__ void compute_G_kernel(const float* __restrict__ fe) {
    int i = blockIdx.x, j = threadIdx.x;
    const float4* a = (const float4*)(fe + i * HID);
    const float4* b = (const float4*)(fe + j * HID);
    float s = 0.f;
#pragma unroll 8
    for (int k = 0; k < HID / 4; k++) {
        float4 x = a[k], y = b[k];
        s = fmaf(x.x, y.x, fmaf(x.y, y.y, fmaf(x.z, y.z, fmaf(x.w, y.w, s))));
    }
    d_G[i * NF + j] = s;
}

// Pack rc_W [K=256][N=256] into m16n8k16 B-fragment order, split bf16 hi/lo.
// idx = ((ks*32)+nt)*32+lane ; b0: k=ks*16+(lane%4)*2+{0,1}, n=nt*8+lane/4 ; b1: k+8
__global__ void prep_rcW_frag(const float* __restrict__ W) {
    int idx = blockIdx.x * 256 + threadIdx.x;
    int lane = idx & 31, nt = (idx >> 5) & 31, ks = idx >> 10;
    int n = nt * 8 + (lane >> 2);
    int k0 = ks * 16 + (lane & 3) * 2;
    float w00 = W[k0 * HID + n], w01 = W[(k0 + 1) * HID + n];
    float w10 = W[(k0 + 8) * HID + n], w11 = W[(k0 + 9) * HID + n];
    __nv_bfloat16 h00 = __float2bfloat16(w00), h01 = __float2bfloat16(w01);
    __nv_bfloat16 h10 = __float2bfloat16(w10), h11 = __float2bfloat16(w11);
    uint2 vh, vl;
    vh.x = pack_bf(h00, h01);
    vh.y = pack_bf(h10, h11);
    vl.x = pack_bf(__float2bfloat16(w00 - __bfloat162float(h00)),
                   __float2bfloat16(w01 - __bfloat162float(h01)));
    vl.y = pack_bf(__float2bfloat16(w10 - __bfloat162float(h10)),
                   __float2bfloat16(w11 - __bfloat162float(h11)));
    d_Wfh[idx] = vh;
    d_Wfl[idx] = vl;
}

// ---------------- fused kernel ----------------
#define R1R 4
#define SMEM_SZ (32768 + 8192 + 2 * 32 * YS * 2)  // sm_h + sm_f + ybh + ybl = 74752

template <int K, int ASTRIDE>
__device__ __forceinline__ void gemm_n256(const float* __restrict__ W, const float* As,
                                          int lane, unsigned long long acc[R1R][4]) {
    const int c0 = lane * 4;
#pragma unroll 1
    for (int k = 0; k < K; k += 4) {
        float4 a4[R1R];
#pragma unroll
        for (int r = 0; r < R1R; r++) a4[r] = *(const float4*)(As + r * ASTRIDE + k);
#pragma unroll
        for (int kk = 0; kk < 4; kk++) {
            ulonglong2 wlo = *(const ulonglong2*)(W + (k + kk) * 256 + c0);
            ulonglong2 whi = *(const ulonglong2*)(W + (k + kk) * 256 + c0 + 128);
#pragma unroll
            for (int r = 0; r < R1R; r++) {
                float av = ((const float*)&a4[r])[kk];
                unsigned long long aa = pk2(av, av);
                fma2(acc[r][0], aa, wlo.x);
                fma2(acc[r][1], aa, wlo.y);
                fma2(acc[r][2], aa, whi.x);
                fma2(acc[r][3], aa, whi.y);
            }
        }
    }
}

extern "C" __global__ void __launch_bounds__(256, 2)
arn_fused(const float* __restrict__ known_mask, const int* __restrict__ obs_idx,
          const int* __restrict__ obs_mask_idx, const int* __restrict__ attr_idx,
          const float* __restrict__ obs_embs,
          const float* __restrict__ rm_W1, const float* __restrict__ rm_b1,
          const float* __restrict__ rm_W2, const float* __restrict__ rm_b2,
          const float* __restrict__ rr_W, const float* __restrict__ rr_b,
          const float* __restrict__ rc_b, float* __restrict__ out, int E) {
    extern __shared__ __align__(16) char smem[];
    float* sm_h = (float*)smem;                              // 32*256 f32
    float* sm_f = (float*)(smem + 32768);                    // 32*64 f32
    __nv_bfloat16* ybh = (__nv_bfloat16*)(smem + 40960);     // 32*YS bf16
    __nv_bfloat16* ybl = ybh + 32 * YS;

    const int w = threadIdx.x >> 5;
    const int lane = threadIdx.x & 31;
    const int row0 = w * R1R;
    const long bb = (long)blockIdx.x * 32;
    const long base = bb + row0;
    const int c0 = lane * 4;

    int oiv[R1R], atv[R1R], omiv[R1R];
#pragma unroll
    for (int r = 0; r < R1R; r++) {
        long e = base + r;
        long ec = (e < E) ? e : (long)(E - 1);
        oiv[r] = obs_idx[ec];
        omiv[r] = obs_mask_idx[ec];
        atv[r] = attr_idx[ec];
    }

    // ---- Phase A: m = softmax(known_mask[omi] * (1 - e_attr)) over F=64 ----
#pragma unroll
    for (int r = 0; r < R1R; r++) {
        const float* km = known_mask + (long)omiv[r] * NF;
        float v0 = km[lane];
        float v1 = km[lane + 32];
        if (lane == atv[r]) v0 = 0.f;
        if (lane + 32 == atv[r]) v1 = 0.f;
        float mx = fmaxf(v0, v1);
#pragma unroll
        for (int o = 16; o > 0; o >>= 1) mx = fmaxf(mx, __shfl_xor_sync(0xffffffffu, mx, o));
        float e0 = expf(v0 - mx), e1 = expf(v1 - mx);
        float s = e0 + e1;
#pragma unroll
        for (int o = 16; o > 0; o >>= 1) s += __shfl_xor_sync(0xffffffffu, s, o);
        float inv = 1.f / s;
        sm_f[(row0 + r) * NF + lane] = e0 * inv;
        sm_f[(row0 + r) * NF + lane + 32] = e1 * inv;
    }
    __syncwarp();

    // ---- Phase B: h1 = gelu(m @ rm_W1 + b1) ----
    {
        unsigned long long acc[R1R][4] = {};
        gemm_n256<NF, NF>(rm_W1, sm_f + row0 * NF, lane, acc);
        float4 bA = *(const float4*)(rm_b1 + c0);
        float4 bB = *(const float4*)(rm_b1 + c0 + 128);
#pragma unroll
        for (int r = 0; r < R1R; r++) {
            float v[8];
            up2(acc[r][0], v[0], v[1]);
            up2(acc[r][1], v[2], v[3]);
            up2(acc[r][2], v[4], v[5]);
            up2(acc[r][3], v[6], v[7]);
            float4 oA, oB;
            oA.x = gelu_exact(v[0] + bA.x);
            oA.y = gelu_exact(v[1] + bA.y);
            oA.z = gelu_exact(v[2] + bA.z);
            oA.w = gelu_exact(v[3] + bA.w);
            oB.x = gelu_exact(v[4] + bB.x);
            oB.y = gelu_exact(v[5] + bB.y);
            oB.z = gelu_exact(v[6] + bB.z);
            oB.w = gelu_exact(v[7] + bB.w);
            *(float4*)(sm_h + (row0 + r) * HID + c0) = oA;
            *(float4*)(sm_h + (row0 + r) * HID + c0 + 128) = oB;
        }
    }
    __syncwarp();

    // ---- Phase C: mJ = gelu(h1 @ rm_W2 + b2); x = G[attr] * mJ ----
    {
        unsigned long long accC[R1R] = {};
        const int cc = lane * 2;
#pragma unroll 1
        for (int k = 0; k < HID; k += 4) {
            float4 a4[R1R];
#pragma unroll
            for (int r = 0; r < R1R; r++) a4[r] = *(const float4*)(sm_h + (row0 + r) * HID + k);
#pragma unroll
            for (int kk = 0; kk < 4; kk++) {
                unsigned long long wp = *(const unsigned long long*)(rm_W2 + (k + kk) * NF + cc);
#pragma unroll
                for (int r = 0; r < R1R; r++) {
                    float av = ((const float*)&a4[r])[kk];
                    fma2(accC[r], pk2(av, av), wp);
                }
            }
        }
        float2 b2v = *(const float2*)(rm_b2 + cc);
#pragma unroll
        for (int r = 0; r < R1R; r++) {
            float x0, x1;
            up2(accC[r], x0, x1);
            x0 = gelu_exact(x0 + b2v.x);
            x1 = gelu_exact(x1 + b2v.y);
            float2 g = *(const float2*)(d_G + atv[r] * NF + cc);
            sm_f[(row0 + r) * NF + cc] = x0 * g.x;
            sm_f[(row0 + r) * NF + cc + 1] = x1 * g.y;
        }
    }
    __syncwarp();

    // ---- Phase D: a = gelu(x @ rr_W + b); y = obs_h * a -> split bf16 to smem ----
    {
        unsigned long long acc[R1R][4] = {};
        gemm_n256<NF, NF>(rr_W, sm_f + row0 * NF, lane, acc);
        float4 bA = *(const float4*)(rr_b + c0);
        float4 bB = *(const float4*)(rr_b + c0 + 128);
#pragma unroll
        for (int r = 0; r < R1R; r++) {
            float v[8];
            up2(acc[r][0], v[0], v[1]);
            up2(acc[r][1], v[2], v[3]);
            up2(acc[r][2], v[4], v[5]);
            up2(acc[r][3], v[6], v[7]);
            float4 hA = *(const float4*)(obs_embs + (long)oiv[r] * HID + c0);
            float4 hB = *(const float4*)(obs_embs + (long)oiv[r] * HID + c0 + 128);
            float4 oA, oB;
            oA.x = gelu_exact(v[0] + bA.x) * hA.x;
            oA.y = gelu_exact(v[1] + bA.y) * hA.y;
            oA.z = gelu_exact(v[2] + bA.z) * hA.z;
            oA.w = gelu_exact(v[3] + bA.w) * hA.w;
            oB.x = gelu_exact(v[4] + bB.x) * hB.x;
            oB.y = gelu_exact(v[5] + bB.y) * hB.y;
            oB.z = gelu_exact(v[6] + bB.z) * hB.z;
            oB.w = gelu_exact(v[7] + bB.w) * hB.w;
            uint2 ph, pl;
            split4(oA, ph, pl);
            *(uint2*)(ybh + (row0 + r) * YS + c0) = ph;
            *(uint2*)(ybl + (row0 + r) * YS + c0) = pl;
            split4(oB, ph, pl);
            *(uint2*)(ybh + (row0 + r) * YS + c0 + 128) = ph;
            *(uint2*)(ybl + (row0 + r) * YS + c0 + 128) = pl;
        }
    }
    __syncthreads();

    // ---- Phase E: out = gelu(y @ rc_W + rc_b) via mma.sync bf16 3-pass ----
    // warp w: rows (w&1)*16..+15, n cols (w>>1)*64..+63  (n-tiles ntg0..ntg0+7)
    {
        const int mrow0 = (w & 1) * 16;
        const int ntg0 = (w >> 1) * 8;
        float acc[8][4] = {};
        const int arow = mrow0 + (lane >> 2);
#pragma unroll 1
        for (int ks = 0; ks < 16; ks++) {
            const int acol = ks * 16 + (lane & 3) * 2;
            unsigned ah0 = *(const unsigned*)(ybh + arow * YS + acol);
            unsigned ah1 = *(const unsigned*)(ybh + (arow + 8) * YS + acol);
            unsigned ah2 = *(const unsigned*)(ybh + arow * YS + acol + 8);
            unsigned ah3 = *(const unsigned*)(ybh + (arow + 8) * YS + acol + 8);
            unsigned al0 = *(const unsigned*)(ybl + arow * YS + acol);
            unsigned al1 = *(const unsigned*)(ybl + (arow + 8) * YS + acol);
            unsigned al2 = *(const unsigned*)(ybl + arow * YS + acol + 8);
            unsigned al3 = *(const unsigned*)(ybl + (arow + 8) * YS + acol + 8);
            const uint2* Wh = d_Wfh + (ks * 32 + ntg0) * 32 + lane;
            const uint2* Wl = d_Wfl + (ks * 32 + ntg0) * 32 + lane;
#pragma unroll
            for (int j = 0; j < 8; j++) {
                uint2 bh = Wh[j * 32];
                uint2 bl = Wl[j * 32];
                mma_bf16(acc[j], ah0, ah1, ah2, ah3, bh.x, bh.y);
                mma_bf16(acc[j], al0, al1, al2, al3, bh.x, bh.y);
                mma_bf16(acc[j], ah0, ah1, ah2, ah3, bl.x, bl.y);
            }
        }
        // epilogue: c[j] lanes map (row=arow[+8], col=(ntg0+j)*8+(lane&3)*2 +{0,1})
        const long e0 = bb + arow;
        const long e1 = e0 + 8;
        const bool w0 = (e0 < (long)E), w1 = (e1 < (long)E);
#pragma unroll
        for (int j = 0; j < 8; j++) {
            const int col = (ntg0 + j) * 8 + (lane & 3) * 2;
            float2 bv = *(const float2*)(rc_b + col);
            if (w0) {
                float2 o;
                o.x = gelu_exact(acc[j][0] + bv.x);
                o.y = gelu_exact(acc[j][1] + bv.y);
                *(float2*)(out + e0 * HID + col) = o;
            }
            if (w1) {
                float2 o;
                o.x = gelu_exact(acc[j][2] + bv.x);
                o.y = gelu_exact(acc[j][3] + bv.y);
                *(float2*)(out + e1 * HID + col) = o;
            }
        }
    }
}

// ---------------- launch ----------------
extern "C" void kernel_launch(void* const* d_in, const int* in_sizes, int n_in,
                              void* d_out, int out_size) {
    const float* known_mask = (const float*)d_in[0];
    const int* obs_idx = (const int*)d_in[1];
    const int* obs_mask_idx = (const int*)d_in[2];
    const int* attr_idx = (const int*)d_in[3];
    const float* obs_embs = (const float*)d_in[4];
    const float* feature_emb = (const float*)d_in[5];
    const float* rm_W1 = (const float*)d_in[6];
    const float* rm_b1 = (const float*)d_in[7];
    const float* rm_W2 = (const float*)d_in[8];
    const float* rm_b2 = (const float*)d_in[9];
    const float* rr_W = (const float*)d_in[10];
    const float* rr_b = (const float*)d_in[11];
    const float* rc_W = (const float*)d_in[12];
    const float* rc_b = (const float*)d_in[13];
    int E = in_sizes[1];

    cudaFuncSetAttribute(arn_fused, cudaFuncAttributeMaxDynamicSharedMemorySize, SMEM_SZ);

    compute_G_kernel<<<NF, NF>>>(feature_emb);
    prep_rcW_frag<<<64, 256>>>(rc_W);
    int grid = (E + 31) / 32;
    arn_fused<<<grid, 256, SMEM_SZ>>>(known_mask, obs_idx, obs_mask_idx, attr_idx, obs_embs,
                                      rm_W1, rm_b1, rm_W2, rm_b2, rr_W, rr_b, rc_b,
                                      (float*)d_out, E);
}

// round 6
// speedup vs baseline: 2.3550x; 1.6151x over previous
#include <cuda_runtime.h>
#include <cuda_bf16.h>
#include <math.h>

#define HID 256
#define NF  64
#define YS  264   // bf16 row stride, 256-col tiles (conflict-free a-frag LDS)
#define XS  72    // bf16 row stride, 64-col tiles
#define NRMAX 100352

// ---------------- device scratch ----------------
__device__ float d_G[NF * NF];
__device__ float d_P[(size_t)NRMAX * HID];  // known_mask @ rm_W1
__device__ float d_rowsum[NRMAX];
__device__ float d_S[HID];  // colsum(rm_W1)
__device__ uint2 d_Wfh[16 * 32 * 32], d_Wfl[16 * 32 * 32];    // rc_W frags
__device__ uint2 d_W2fh[16 * 8 * 32], d_W2fl[16 * 8 * 32];    // rm_W2 frags
__device__ uint2 d_Wrfh[4 * 32 * 32], d_Wrfl[4 * 32 * 32];    // rr_W frags
__device__ uint2 d_W1fh[4 * 32 * 32], d_W1fl[4 * 32 * 32];    // rm_W1 frags (for P prep)

// ---------------- helpers ----------------
__device__ __forceinline__ float gelu_exact(float x) {
    return 0.5f * x * (1.f + erff(x * 0.7071067811865476f));
}
__device__ __forceinline__ unsigned pack_bf(__nv_bfloat16 a, __nv_bfloat16 b) {
    return (unsigned)__bfloat16_as_ushort(a) | ((unsigned)__bfloat16_as_ushort(b) << 16);
}
__device__ __forceinline__ void split2(float x, float y, unsigned& ph, unsigned& pl) {
    __nv_bfloat16 h0 = __float2bfloat16(x), h1 = __float2bfloat16(y);
    ph = pack_bf(h0, h1);
    pl = pack_bf(__float2bfloat16(x - __bfloat162float(h0)),
                 __float2bfloat16(y - __bfloat162float(h1)));
}
__device__ __forceinline__ void mma_bf16(float c[4], unsigned a0, unsigned a1, unsigned a2,
                                         unsigned a3, unsigned b0, unsigned b1) {
    asm("mma.sync.aligned.m16n8k16.row.col.f32.bf16.bf16.f32 "
        "{%0,%1,%2,%3},{%4,%5,%6,%7},{%8,%9},{%0,%1,%2,%3};"
        : "+f"(c[0]), "+f"(c[1]), "+f"(c[2]), "+f"(c[3])
        : "r"(a0), "r"(a1), "r"(a2), "r"(a3), "r"(b0), "r"(b1));
}

// ---------------- prep kernels ----------------
__global__ void compute_G_kernel(const float* __restrict__ fe) {
    int i = blockIdx.x, j = threadIdx.x;
    const float4* a = (const float4*)(fe + i * HID);
    const float4* b = (const float4*)(fe + j * HID);
    float s = 0.f;
#pragma unroll 8
    for (int k = 0; k < HID / 4; k++) {
        float4 x = a[k], y = b[k];
        s = fmaf(x.x, y.x, fmaf(x.y, y.y, fmaf(x.z, y.z, fmaf(x.w, y.w, s))));
    }
    d_G[i * NF + j] = s;
}

// Pack W [K x N] row-major into m16n8k16 B-frag order (NT n-tiles), split hi/lo.
// ID selects the destination __device__ arrays IN DEVICE CODE (host cannot take
// the address of a __device__ symbol).
template <int ID>
__global__ void prep_frag(const float* __restrict__ W, int N, int NT) {
    uint2* dh = (ID == 0) ? d_Wfh : (ID == 1) ? d_W2fh : (ID == 2) ? d_Wrfh : d_W1fh;
    uint2* dl = (ID == 0) ? d_Wfl : (ID == 1) ? d_W2fl : (ID == 2) ? d_Wrfl : d_W1fl;
    int idx = blockIdx.x * 256 + threadIdx.x;
    int lane = idx & 31, nt = (idx >> 5) % NT, ks = idx / (NT * 32);
    int n = nt * 8 + (lane >> 2);
    int k0 = ks * 16 + (lane & 3) * 2;
    float w00 = W[k0 * N + n], w01 = W[(k0 + 1) * N + n];
    float w10 = W[(k0 + 8) * N + n], w11 = W[(k0 + 9) * N + n];
    __nv_bfloat16 h00 = __float2bfloat16(w00), h01 = __float2bfloat16(w01);
    __nv_bfloat16 h10 = __float2bfloat16(w10), h11 = __float2bfloat16(w11);
    uint2 vh, vl;
    vh.x = pack_bf(h00, h01);
    vh.y = pack_bf(h10, h11);
    vl.x = pack_bf(__float2bfloat16(w00 - __bfloat162float(h00)),
                   __float2bfloat16(w01 - __bfloat162float(h01)));
    vl.y = pack_bf(__float2bfloat16(w10 - __bfloat162float(h10)),
                   __float2bfloat16(w11 - __bfloat162float(h11)));
    dh[idx] = vh;
    dl[idx] = vl;
}

__global__ void prep_S(const float* __restrict__ W1) {
    int c = threadIdx.x;
    float s = 0.f;
#pragma unroll
    for (int k = 0; k < NF; k++) s += W1[k * HID + c];
    d_S[c] = s;
}

// P = known_mask @ rm_W1 via 2-pass bf16 mma (A binary -> exact in bf16); also rowsums.
__global__ void __launch_bounds__(256, 2)
prep_P(const float* __restrict__ km, int nr) {
    __shared__ __align__(16) __nv_bfloat16 kmb[32 * XS];
    const int tid = threadIdx.x, w = tid >> 5, lane = tid & 31;
    const int rbase = blockIdx.x * 32;

    for (int i = tid; i < 32 * 64; i += 256) {
        int row = i >> 6, col = i & 63;
        int gr = rbase + row;
        float v = (gr < nr) ? km[(long)gr * 64 + col] : 0.f;
        kmb[row * XS + col] = __float2bfloat16(v);
    }
    // rowsums (warp w handles rows w*4..w*4+3)
#pragma unroll
    for (int r = 0; r < 4; r++) {
        int row = w * 4 + r, gr = rbase + row;
        float v = 0.f;
        if (gr < nr) v = km[(long)gr * 64 + lane] + km[(long)gr * 64 + lane + 32];
#pragma unroll
        for (int o = 16; o > 0; o >>= 1) v += __shfl_xor_sync(0xffffffffu, v, o);
        if (lane == 0 && gr < nr) d_rowsum[gr] = v;
    }
    __syncthreads();

    const int mrow0 = (w & 1) * 16, g0 = (w >> 1) * 8;
    const int arow = mrow0 + (lane >> 2);
    float acc[8][4] = {};
#pragma unroll
    for (int ks = 0; ks < 4; ks++) {
        const int acol = ks * 16 + (lane & 3) * 2;
        unsigned a0 = *(const unsigned*)(kmb + arow * XS + acol);
        unsigned a1 = *(const unsigned*)(kmb + (arow + 8) * XS + acol);
        unsigned a2 = *(const unsigned*)(kmb + arow * XS + acol + 8);
        unsigned a3 = *(const unsigned*)(kmb + (arow + 8) * XS + acol + 8);
        const uint2* Wh = d_W1fh + (ks * 32 + g0) * 32 + lane;
        const uint2* Wl = d_W1fl + (ks * 32 + g0) * 32 + lane;
#pragma unroll
        for (int j = 0; j < 8; j++) {
            uint2 bh = Wh[j * 32], bl = Wl[j * 32];
            mma_bf16(acc[j], a0, a1, a2, a3, bh.x, bh.y);
            mma_bf16(acc[j], a0, a1, a2, a3, bl.x, bl.y);
        }
    }
    const int r0 = rbase + arow, r1 = r0 + 8;
#pragma unroll
    for (int j = 0; j < 8; j++) {
        const int col = (g0 + j) * 8 + (lane & 3) * 2;
        if (r0 < nr) *(float2*)(d_P + (long)r0 * HID + col) = make_float2(acc[j][0], acc[j][1]);
        if (r1 < nr) *(float2*)(d_P + (long)r1 * HID + col) = make_float2(acc[j][2], acc[j][3]);
    }
}

// ---------------- fused main kernel ----------------
extern "C" __global__ void __launch_bounds__(256, 2)
arn_fused(const float* __restrict__ known_mask, const int* __restrict__ obs_idx,
          const int* __restrict__ obs_mask_idx, const int* __restrict__ attr_idx,
          const float* __restrict__ obs_embs,
          const float* __restrict__ rm_W1, const float* __restrict__ rm_b1,
          const float* __restrict__ rm_b2, const float* __restrict__ rr_b,
          const float* __restrict__ rc_b, float* __restrict__ out, int E) {
    __shared__ __align__(16) __nv_bfloat16 ybh[32 * YS];
    __shared__ __align__(16) __nv_bfloat16 ybl[32 * YS];
    __shared__ __align__(16) __nv_bfloat16 xbh[32 * XS];
    __shared__ __align__(16) __nv_bfloat16 xbl[32 * XS];
    __shared__ int satv[32], soiv[32];

    const int w = threadIdx.x >> 5;
    const int lane = threadIdx.x & 31;
    const int row0 = w * 4;
    const long bb = (long)blockIdx.x * 32;
    const long base = bb + row0;

    int oiv[4], atv[4], omiv[4];
#pragma unroll
    for (int r = 0; r < 4; r++) {
        long e = base + r;
        long ec = (e < E) ? e : (long)(E - 1);
        oiv[r] = obs_idx[ec];
        omiv[r] = obs_mask_idx[ec];
        atv[r] = attr_idx[ec];
    }
    if (lane == 0) {
#pragma unroll
        for (int r = 0; r < 4; r++) {
            satv[row0 + r] = atv[r];
            soiv[row0 + r] = oiv[r];
        }
    }

    // ---- Phase AB (closed-form softmax + precomputed P): h1 -> ybh/ybl ----
    {
        const int cc0 = lane * 8;
        const float E1M1 = 1.7182818284590452f;  // e - 1
#pragma unroll
        for (int r = 0; r < 4; r++) {
            float t = known_mask[(long)omiv[r] * NF + atv[r]];  // 0 or 1
            float c = d_rowsum[omiv[r]] - t;
            float Z = fmaf(c, E1M1, 64.f);
            float beta = 1.f / Z;
            float dco = E1M1 * beta;  // alpha - beta
            const float* Prow = d_P + (long)omiv[r] * HID + cc0;
            float4 p0 = *(const float4*)(Prow);
            float4 p1 = *(const float4*)(Prow + 4);
            if (t != 0.f) {
                const float* w1a = rm_W1 + atv[r] * HID + cc0;
                float4 q0 = *(const float4*)(w1a);
                float4 q1 = *(const float4*)(w1a + 4);
                p0.x -= q0.x; p0.y -= q0.y; p0.z -= q0.z; p0.w -= q0.w;
                p1.x -= q1.x; p1.y -= q1.y; p1.z -= q1.z; p1.w -= q1.w;
            }
            float4 s0 = *(const float4*)(d_S + cc0);
            float4 s1 = *(const float4*)(d_S + cc0 + 4);
            float4 b0 = *(const float4*)(rm_b1 + cc0);
            float4 b1v = *(const float4*)(rm_b1 + cc0 + 4);
            float h[8];
            h[0] = gelu_exact(fmaf(beta, s0.x, fmaf(dco, p0.x, b0.x)));
            h[1] = gelu_exact(fmaf(beta, s0.y, fmaf(dco, p0.y, b0.y)));
            h[2] = gelu_exact(fmaf(beta, s0.z, fmaf(dco, p0.z, b0.z)));
            h[3] = gelu_exact(fmaf(beta, s0.w, fmaf(dco, p0.w, b0.w)));
            h[4] = gelu_exact(fmaf(beta, s1.x, fmaf(dco, p1.x, b1v.x)));
            h[5] = gelu_exact(fmaf(beta, s1.y, fmaf(dco, p1.y, b1v.y)));
            h[6] = gelu_exact(fmaf(beta, s1.z, fmaf(dco, p1.z, b1v.z)));
            h[7] = gelu_exact(fmaf(beta, s1.w, fmaf(dco, p1.w, b1v.w)));
            uint4 uh, ul;
            split2(h[0], h[1], uh.x, ul.x);
            split2(h[2], h[3], uh.y, ul.y);
            split2(h[4], h[5], uh.z, ul.z);
            split2(h[6], h[7], uh.w, ul.w);
            *(uint4*)(ybh + (row0 + r) * YS + cc0) = uh;
            *(uint4*)(ybl + (row0 + r) * YS + cc0) = ul;
        }
    }
    __syncthreads();

    // ---- Phase C: mJ = gelu(h1 @ rm_W2 + b2); x = G[attr] * mJ -> xbh/xbl ----
    {
        const int mrow0 = (w & 1) * 16, q0 = (w >> 1) * 2;
        const int arow = mrow0 + (lane >> 2);
        float acc[2][4] = {};
#pragma unroll 1
        for (int ks = 0; ks < 16; ks++) {
            const int acol = ks * 16 + (lane & 3) * 2;
            unsigned ah0 = *(const unsigned*)(ybh + arow * YS + acol);
            unsigned ah1 = *(const unsigned*)(ybh + (arow + 8) * YS + acol);
            unsigned ah2 = *(const unsigned*)(ybh + arow * YS + acol + 8);
            unsigned ah3 = *(const unsigned*)(ybh + (arow + 8) * YS + acol + 8);
            unsigned al0 = *(const unsigned*)(ybl + arow * YS + acol);
            unsigned al1 = *(const unsigned*)(ybl + (arow + 8) * YS + acol);
            unsigned al2 = *(const unsigned*)(ybl + arow * YS + acol + 8);
            unsigned al3 = *(const unsigned*)(ybl + (arow + 8) * YS + acol + 8);
            const uint2* Wh = d_W2fh + (ks * 8 + q0) * 32 + lane;
            const uint2* Wl = d_W2fl + (ks * 8 + q0) * 32 + lane;
#pragma unroll
            for (int j = 0; j < 2; j++) {
                uint2 bh = Wh[j * 32], bl = Wl[j * 32];
                mma_bf16(acc[j], ah0, ah1, ah2, ah3, bh.x, bh.y);
                mma_bf16(acc[j], al0, al1, al2, al3, bh.x, bh.y);
                mma_bf16(acc[j], ah0, ah1, ah2, ah3, bl.x, bl.y);
            }
        }
        const int at0 = satv[arow], at1 = satv[arow + 8];
#pragma unroll
        for (int j = 0; j < 2; j++) {
            const int col = (q0 + j) * 8 + (lane & 3) * 2;
            float2 b2v = *(const float2*)(rm_b2 + col);
            float2 g0 = *(const float2*)(d_G + at0 * NF + col);
            float2 g1 = *(const float2*)(d_G + at1 * NF + col);
            float x00 = gelu_exact(acc[j][0] + b2v.x) * g0.x;
            float x01 = gelu_exact(acc[j][1] + b2v.y) * g0.y;
            float x10 = gelu_exact(acc[j][2] + b2v.x) * g1.x;
            float x11 = gelu_exact(acc[j][3] + b2v.y) * g1.y;
            unsigned ph, pl;
            split2(x00, x01, ph, pl);
            *(unsigned*)(xbh + arow * XS + col) = ph;
            *(unsigned*)(xbl + arow * XS + col) = pl;
            split2(x10, x11, ph, pl);
            *(unsigned*)(xbh + (arow + 8) * XS + col) = ph;
            *(unsigned*)(xbl + (arow + 8) * XS + col) = pl;
        }
    }
    __syncthreads();

    // ---- Phase D: a = gelu(x @ rr_W + rr_b); y = obs_h * a -> ybh/ybl ----
    {
        const int mrow0 = (w & 1) * 16, g0 = (w >> 1) * 8;
        const int arow = mrow0 + (lane >> 2);
        float acc[8][4] = {};
#pragma unroll
        for (int ks = 0; ks < 4; ks++) {
            const int acol = ks * 16 + (lane & 3) * 2;
            unsigned ah0 = *(const unsigned*)(xbh + arow * XS + acol);
            unsigned ah1 = *(const unsigned*)(xbh + (arow + 8) * XS + acol);
            unsigned ah2 = *(const unsigned*)(xbh + arow * XS + acol + 8);
            unsigned ah3 = *(const unsigned*)(xbh + (arow + 8) * XS + acol + 8);
            unsigned al0 = *(const unsigned*)(xbl + arow * XS + acol);
            unsigned al1 = *(const unsigned*)(xbl + (arow + 8) * XS + acol);
            unsigned al2 = *(const unsigned*)(xbl + arow * XS + acol + 8);
            unsigned al3 = *(const unsigned*)(xbl + (arow + 8) * XS + acol + 8);
            const uint2* Wh = d_Wrfh + (ks * 32 + g0) * 32 + lane;
            const uint2* Wl = d_Wrfl + (ks * 32 + g0) * 32 + lane;
#pragma unroll
            for (int j = 0; j < 8; j++) {
                uint2 bh = Wh[j * 32], bl = Wl[j * 32];
                mma_bf16(acc[j], ah0, ah1, ah2, ah3, bh.x, bh.y);
                mma_bf16(acc[j], al0, al1, al2, al3, bh.x, bh.y);
                mma_bf16(acc[j], ah0, ah1, ah2, ah3, bl.x, bl.y);
            }
        }
        const int oi0 = soiv[arow], oi1 = soiv[arow + 8];
#pragma unroll
        for (int j = 0; j < 8; j++) {
            const int col = (g0 + j) * 8 + (lane & 3) * 2;
            float2 rb = *(const float2*)(rr_b + col);
            float2 h0 = *(const float2*)(obs_embs + (long)oi0 * HID + col);
            float2 h1 = *(const float2*)(obs_embs + (long)oi1 * HID + col);
            float y00 = gelu_exact(acc[j][0] + rb.x) * h0.x;
            float y01 = gelu_exact(acc[j][1] + rb.y) * h0.y;
            float y10 = gelu_exact(acc[j][2] + rb.x) * h1.x;
            float y11 = gelu_exact(acc[j][3] + rb.y) * h1.y;
            unsigned ph, pl;
            split2(y00, y01, ph, pl);
            *(unsigned*)(ybh + arow * YS + col) = ph;
            *(unsigned*)(ybl + arow * YS + col) = pl;
            split2(y10, y11, ph, pl);
            *(unsigned*)(ybh + (arow + 8) * YS + col) = ph;
            *(unsigned*)(ybl + (arow + 8) * YS + col) = pl;
        }
    }
    __syncthreads();

    // ---- Phase E: out = gelu(y @ rc_W + rc_b) ----
    {
        const int mrow0 = (w & 1) * 16, g0 = (w >> 1) * 8;
        const int arow = mrow0 + (lane >> 2);
        float acc[8][4] = {};
#pragma unroll 1
        for (int ks = 0; ks < 16; ks++) {
            const int acol = ks * 16 + (lane & 3) * 2;
            unsigned ah0 = *(const unsigned*)(ybh + arow * YS + acol);
            unsigned ah1 = *(const unsigned*)(ybh + (arow + 8) * YS + acol);
            unsigned ah2 = *(const unsigned*)(ybh + arow * YS + acol + 8);
            unsigned ah3 = *(const unsigned*)(ybh + (arow + 8) * YS + acol + 8);
            unsigned al0 = *(const unsigned*)(ybl + arow * YS + acol);
            unsigned al1 = *(const unsigned*)(ybl + (arow + 8) * YS + acol);
            unsigned al2 = *(const unsigned*)(ybl + arow * YS + acol + 8);
            unsigned al3 = *(const unsigned*)(ybl + (arow + 8) * YS + acol + 8);
            const uint2* Wh = d_Wfh + (ks * 32 + g0) * 32 + lane;
            const uint2* Wl = d_Wfl + (ks * 32 + g0) * 32 + lane;
#pragma unroll
            for (int j = 0; j < 8; j++) {
                uint2 bh = Wh[j * 32], bl = Wl[j * 32];
                mma_bf16(acc[j], ah0, ah1, ah2, ah3, bh.x, bh.y);
                mma_bf16(acc[j], al0, al1, al2, al3, bh.x, bh.y);
                mma_bf16(acc[j], ah0, ah1, ah2, ah3, bl.x, bl.y);
            }
        }
        const long e0 = bb + arow, e1 = e0 + 8;
        const bool w0 = (e0 < (long)E), w1 = (e1 < (long)E);
#pragma unroll
        for (int j = 0; j < 8; j++) {
            const int col = (g0 + j) * 8 + (lane & 3) * 2;
            float2 bv = *(const float2*)(rc_b + col);
            if (w0) {
                float2 o;
                o.x = gelu_exact(acc[j][0] + bv.x);
                o.y = gelu_exact(acc[j][1] + bv.y);
                *(float2*)(out + e0 * HID + col) = o;
            }
            if (w1) {
                float2 o;
                o.x = gelu_exact(acc[j][2] + bv.x);
                o.y = gelu_exact(acc[j][3] + bv.y);
                *(float2*)(out + e1 * HID + col) = o;
            }
        }
    }
}

// ---------------- launch ----------------
extern "C" void kernel_launch(void* const* d_in, const int* in_sizes, int n_in,
                              void* d_out, int out_size) {
    const float* known_mask = (const float*)d_in[0];
    const int* obs_idx = (const int*)d_in[1];
    const int* obs_mask_idx = (const int*)d_in[2];
    const int* attr_idx = (const int*)d_in[3];
    const float* obs_embs = (const float*)d_in[4];
    const float* feature_emb = (const float*)d_in[5];
    const float* rm_W1 = (const float*)d_in[6];
    const float* rm_b1 = (const float*)d_in[7];
    const float* rm_W2 = (const float*)d_in[8];
    const float* rm_b2 = (const float*)d_in[9];
    const float* rr_W = (const float*)d_in[10];
    const float* rr_b = (const float*)d_in[11];
    const float* rc_W = (const float*)d_in[12];
    const float* rc_b = (const float*)d_in[13];
    int E = in_sizes[1];
    int nr = in_sizes[0] / NF;

    compute_G_kernel<<<NF, NF>>>(feature_emb);
    prep_frag<0><<<64, 256>>>(rc_W, 256, 32);
    prep_frag<1><<<16, 256>>>(rm_W2, 64, 8);
    prep_frag<2><<<16, 256>>>(rr_W, 256, 32);
    prep_frag<3><<<16, 256>>>(rm_W1, 256, 32);
    prep_S<<<1, 256>>>(rm_W1);
    prep_P<<<(nr + 31) / 32, 256>>>(known_mask, nr);

    int grid = (E + 31) / 32;
    arn_fused<<<grid, 256>>>(known_mask, obs_idx, obs_mask_idx, attr_idx, obs_embs,
                             rm_W1, rm_b1, rm_b2, rr_b, rc_b, (float*)d_out, E);
}

// round 7
// speedup vs baseline: 2.3833x; 1.0120x over previous
#include <cuda_runtime.h>
#include <cuda_bf16.h>
#include <math.h>

#define HID 256
#define NF  64
#define YS  264   // bf16 row stride, 256-col tiles (conflict-free a-frag LDS)
#define XS  72    // bf16 row stride, 64-col tiles
#define NRMAX 100352
#define MROWS 64  // edges per CTA

// ---------------- device scratch ----------------
__device__ float d_G[NF * NF];
__device__ float d_P[(size_t)NRMAX * HID];  // known_mask @ rm_W1
__device__ float d_rowsum[NRMAX];
__device__ float d_S[HID];  // colsum(rm_W1)
// interleaved fragment tables: uint4 = {hi.x, hi.y, lo.x, lo.y}
__device__ uint4 d_Wf[16 * 32 * 32];   // rc_W
__device__ uint4 d_W2f[16 * 8 * 32];   // rm_W2
__device__ uint4 d_Wrf[4 * 32 * 32];   // rr_W
__device__ uint4 d_W1f[4 * 32 * 32];   // rm_W1 (for P prep)

// ---------------- helpers ----------------
__device__ __forceinline__ float gelu_exact(float x) {
    return 0.5f * x * (1.f + erff(x * 0.7071067811865476f));
}
__device__ __forceinline__ unsigned pack_bf(__nv_bfloat16 a, __nv_bfloat16 b) {
    return (unsigned)__bfloat16_as_ushort(a) | ((unsigned)__bfloat16_as_ushort(b) << 16);
}
__device__ __forceinline__ void split2(float x, float y, unsigned& ph, unsigned& pl) {
    __nv_bfloat16 h0 = __float2bfloat16(x), h1 = __float2bfloat16(y);
    ph = pack_bf(h0, h1);
    pl = pack_bf(__float2bfloat16(x - __bfloat162float(h0)),
                 __float2bfloat16(y - __bfloat162float(h1)));
}
__device__ __forceinline__ void mma_bf16(float c[4], unsigned a0, unsigned a1, unsigned a2,
                                         unsigned a3, unsigned b0, unsigned b1) {
    asm("mma.sync.aligned.m16n8k16.row.col.f32.bf16.bf16.f32 "
        "{%0,%1,%2,%3},{%4,%5,%6,%7},{%8,%9},{%0,%1,%2,%3};"
        : "+f"(c[0]), "+f"(c[1]), "+f"(c[2]), "+f"(c[3])
        : "r"(a0), "r"(a1), "r"(a2), "r"(a3), "r"(b0), "r"(b1));
}

// ---------------- prep kernels ----------------
__global__ void compute_G_kernel(const float* __restrict__ fe) {
    int i = blockIdx.x, j = threadIdx.x;
    const float4* a = (const float4*)(fe + i * HID);
    const float4* b = (const float4*)(fe + j * HID);
    float s = 0.f;
#pragma unroll 8
    for (int k = 0; k < HID / 4; k++) {
        float4 x = a[k], y = b[k];
        s = fmaf(x.x, y.x, fmaf(x.y, y.y, fmaf(x.z, y.z, fmaf(x.w, y.w, s))));
    }
    d_G[i * NF + j] = s;
}

// Pack W [K x N] row-major into m16n8k16 B-frag order, split bf16 hi/lo, interleaved.
template <int ID>
__global__ void prep_frag(const float* __restrict__ W, int N, int NT) {
    uint4* dst = (ID == 0) ? d_Wf : (ID == 1) ? d_W2f : (ID == 2) ? d_Wrf : d_W1f;
    int idx = blockIdx.x * 256 + threadIdx.x;
    int lane = idx & 31, nt = (idx >> 5) % NT, ks = idx / (NT * 32);
    int n = nt * 8 + (lane >> 2);
    int k0 = ks * 16 + (lane & 3) * 2;
    float w00 = W[k0 * N + n], w01 = W[(k0 + 1) * N + n];
    float w10 = W[(k0 + 8) * N + n], w11 = W[(k0 + 9) * N + n];
    __nv_bfloat16 h00 = __float2bfloat16(w00), h01 = __float2bfloat16(w01);
    __nv_bfloat16 h10 = __float2bfloat16(w10), h11 = __float2bfloat16(w11);
    uint4 v;
    v.x = pack_bf(h00, h01);
    v.y = pack_bf(h10, h11);
    v.z = pack_bf(__float2bfloat16(w00 - __bfloat162float(h00)),
                  __float2bfloat16(w01 - __bfloat162float(h01)));
    v.w = pack_bf(__float2bfloat16(w10 - __bfloat162float(h10)),
                  __float2bfloat16(w11 - __bfloat162float(h11)));
    dst[idx] = v;
}

__global__ void prep_S(const float* __restrict__ W1) {
    int c = threadIdx.x;
    float s = 0.f;
#pragma unroll
    for (int k = 0; k < NF; k++) s += W1[k * HID + c];
    d_S[c] = s;
}

// P = known_mask @ rm_W1 via 2-pass bf16 mma (A binary -> exact); also rowsums.
__global__ void __launch_bounds__(256, 2)
prep_P(const float* __restrict__ km, int nr) {
    __shared__ __align__(16) __nv_bfloat16 kmb[32 * XS];
    const int tid = threadIdx.x, w = tid >> 5, lane = tid & 31;
    const int rbase = blockIdx.x * 32;

    for (int i = tid; i < 32 * 64; i += 256) {
        int row = i >> 6, col = i & 63;
        int gr = rbase + row;
        float v = (gr < nr) ? km[(long)gr * 64 + col] : 0.f;
        kmb[row * XS + col] = __float2bfloat16(v);
    }
#pragma unroll
    for (int r = 0; r < 4; r++) {
        int row = w * 4 + r, gr = rbase + row;
        float v = 0.f;
        if (gr < nr) v = km[(long)gr * 64 + lane] + km[(long)gr * 64 + lane + 32];
#pragma unroll
        for (int o = 16; o > 0; o >>= 1) v += __shfl_xor_sync(0xffffffffu, v, o);
        if (lane == 0 && gr < nr) d_rowsum[gr] = v;
    }
    __syncthreads();

    const int mrow0 = (w & 1) * 16, g0 = (w >> 1) * 8;
    const int arow = mrow0 + (lane >> 2);
    float acc[8][4] = {};
#pragma unroll
    for (int ks = 0; ks < 4; ks++) {
        const int acol = ks * 16 + (lane & 3) * 2;
        unsigned a0 = *(const unsigned*)(kmb + arow * XS + acol);
        unsigned a1 = *(const unsigned*)(kmb + (arow + 8) * XS + acol);
        unsigned a2 = *(const unsigned*)(kmb + arow * XS + acol + 8);
        unsigned a3 = *(const unsigned*)(kmb + (arow + 8) * XS + acol + 8);
        const uint4* Wf = d_W1f + (ks * 32 + g0) * 32 + lane;
#pragma unroll
        for (int j = 0; j < 8; j++) {
            uint4 b = Wf[j * 32];
            mma_bf16(acc[j], a0, a1, a2, a3, b.x, b.y);
            mma_bf16(acc[j], a0, a1, a2, a3, b.z, b.w);
        }
    }
    const int r0 = rbase + arow, r1 = r0 + 8;
#pragma unroll
    for (int j = 0; j < 8; j++) {
        const int col = (g0 + j) * 8 + (lane & 3) * 2;
        if (r0 < nr) *(float2*)(d_P + (long)r0 * HID + col) = make_float2(acc[j][0], acc[j][1]);
        if (r1 < nr) *(float2*)(d_P + (long)r1 * HID + col) = make_float2(acc[j][2], acc[j][3]);
    }
}

// ---------------- fused main kernel: 64 edges per CTA ----------------
// dynamic smem layout (bytes):
//   ybh: 0                (64*YS bf16 = 33792)
//   ybl: 33792
//   xbh: 67584            (64*XS bf16 = 9216)
//   xbl: 76800
//   satv: 86016  (64 int) soiv: 86272 (64 int)
#define SMEM_SZ 86528

extern "C" __global__ void __launch_bounds__(256, 2)
arn_fused(const float* __restrict__ known_mask, const int* __restrict__ obs_idx,
          const int* __restrict__ obs_mask_idx, const int* __restrict__ attr_idx,
          const float* __restrict__ obs_embs,
          const float* __restrict__ rm_W1, const float* __restrict__ rm_b1,
          const float* __restrict__ rm_b2, const float* __restrict__ rr_b,
          const float* __restrict__ rc_b, float* __restrict__ out, int E) {
    extern __shared__ __align__(16) char smem[];
    __nv_bfloat16* ybh = (__nv_bfloat16*)smem;
    __nv_bfloat16* ybl = (__nv_bfloat16*)(smem + 33792);
    __nv_bfloat16* xbh = (__nv_bfloat16*)(smem + 67584);
    __nv_bfloat16* xbl = (__nv_bfloat16*)(smem + 76800);
    int* satv = (int*)(smem + 86016);
    int* soiv = (int*)(smem + 86272);

    const int w = threadIdx.x >> 5;
    const int lane = threadIdx.x & 31;
    const long bb = (long)blockIdx.x * MROWS;

    // ---- Phase AB (closed-form softmax + precomputed P): h1 -> ybh/ybl ----
    {
        const int row0 = w * 8;
        const int cc0 = lane * 8;
        const float E1M1 = 1.7182818284590452f;  // e - 1
#pragma unroll 1
        for (int r = 0; r < 8; r++) {
            long e = bb + row0 + r;
            long ec = (e < E) ? e : (long)(E - 1);
            int oi = obs_idx[ec];
            int omi = obs_mask_idx[ec];
            int at = attr_idx[ec];
            if (lane == 0) {
                satv[row0 + r] = at;
                soiv[row0 + r] = oi;
            }
            float t = known_mask[(long)omi * NF + at];  // 0 or 1
            float c = d_rowsum[omi] - t;
            float Z = fmaf(c, E1M1, 64.f);
            float beta = 1.f / Z;
            float dco = E1M1 * beta;  // alpha - beta
            const float* Prow = d_P + (long)omi * HID + cc0;
            float4 p0 = *(const float4*)(Prow);
            float4 p1 = *(const float4*)(Prow + 4);
            if (t != 0.f) {
                const float* w1a = rm_W1 + at * HID + cc0;
                float4 q0 = *(const float4*)(w1a);
                float4 q1 = *(const float4*)(w1a + 4);
                p0.x -= q0.x; p0.y -= q0.y; p0.z -= q0.z; p0.w -= q0.w;
                p1.x -= q1.x; p1.y -= q1.y; p1.z -= q1.z; p1.w -= q1.w;
            }
            float4 s0 = *(const float4*)(d_S + cc0);
            float4 s1 = *(const float4*)(d_S + cc0 + 4);
            float4 b0 = *(const float4*)(rm_b1 + cc0);
            float4 b1v = *(const float4*)(rm_b1 + cc0 + 4);
            float h[8];
            h[0] = gelu_exact(fmaf(beta, s0.x, fmaf(dco, p0.x, b0.x)));
            h[1] = gelu_exact(fmaf(beta, s0.y, fmaf(dco, p0.y, b0.y)));
            h[2] = gelu_exact(fmaf(beta, s0.z, fmaf(dco, p0.z, b0.z)));
            h[3] = gelu_exact(fmaf(beta, s0.w, fmaf(dco, p0.w, b0.w)));
            h[4] = gelu_exact(fmaf(beta, s1.x, fmaf(dco, p1.x, b1v.x)));
            h[5] = gelu_exact(fmaf(beta, s1.y, fmaf(dco, p1.y, b1v.y)));
            h[6] = gelu_exact(fmaf(beta, s1.z, fmaf(dco, p1.z, b1v.z)));
            h[7] = gelu_exact(fmaf(beta, s1.w, fmaf(dco, p1.w, b1v.w)));
            uint4 uh, ul;
            split2(h[0], h[1], uh.x, ul.x);
            split2(h[2], h[3], uh.y, ul.y);
            split2(h[4], h[5], uh.z, ul.z);
            split2(h[6], h[7], uh.w, ul.w);
            *(uint4*)(ybh + (row0 + r) * YS + cc0) = uh;
            *(uint4*)(ybl + (row0 + r) * YS + cc0) = ul;
        }
    }
    __syncthreads();

    const int mrow0 = (w & 3) * 16;      // 4 row groups of 16
    const int cgrp = (w >> 2);           // 2 col groups of 128
    const int arow = mrow0 + (lane >> 2);

    // ---- Phase C: mJ = gelu(h1 @ rm_W2 + b2); x = G[attr] * mJ -> xbh/xbl ----
    {
        const int q0 = cgrp * 4;  // 4 n-tiles of 8 cols (64 total / 2 groups)
        float acc[4][4] = {};
#pragma unroll 1
        for (int ks = 0; ks < 16; ks++) {
            const int acol = ks * 16 + (lane & 3) * 2;
            unsigned ah0 = *(const unsigned*)(ybh + arow * YS + acol);
            unsigned ah1 = *(const unsigned*)(ybh + (arow + 8) * YS + acol);
            unsigned ah2 = *(const unsigned*)(ybh + arow * YS + acol + 8);
            unsigned ah3 = *(const unsigned*)(ybh + (arow + 8) * YS + acol + 8);
            unsigned al0 = *(const unsigned*)(ybl + arow * YS + acol);
            unsigned al1 = *(const unsigned*)(ybl + (arow + 8) * YS + acol);
            unsigned al2 = *(const unsigned*)(ybl + arow * YS + acol + 8);
            unsigned al3 = *(const unsigned*)(ybl + (arow + 8) * YS + acol + 8);
            const uint4* Wf = d_W2f + (ks * 8 + q0) * 32 + lane;
#pragma unroll
            for (int j = 0; j < 4; j++) {
                uint4 b = Wf[j * 32];
                mma_bf16(acc[j], ah0, ah1, ah2, ah3, b.x, b.y);
                mma_bf16(acc[j], al0, al1, al2, al3, b.x, b.y);
                mma_bf16(acc[j], ah0, ah1, ah2, ah3, b.z, b.w);
            }
        }
        const int at0 = satv[arow], at1 = satv[arow + 8];
#pragma unroll
        for (int j = 0; j < 4; j++) {
            const int col = (q0 + j) * 8 + (lane & 3) * 2;
            float2 b2v = *(const float2*)(rm_b2 + col);
            float2 g0v = *(const float2*)(d_G + at0 * NF + col);
            float2 g1v = *(const float2*)(d_G + at1 * NF + col);
            float x00 = gelu_exact(acc[j][0] + b2v.x) * g0v.x;
            float x01 = gelu_exact(acc[j][1] + b2v.y) * g0v.y;
            float x10 = gelu_exact(acc[j][2] + b2v.x) * g1v.x;
            float x11 = gelu_exact(acc[j][3] + b2v.y) * g1v.y;
            unsigned ph, pl;
            split2(x00, x01, ph, pl);
            *(unsigned*)(xbh + arow * XS + col) = ph;
            *(unsigned*)(xbl + arow * XS + col) = pl;
            split2(x10, x11, ph, pl);
            *(unsigned*)(xbh + (arow + 8) * XS + col) = ph;
            *(unsigned*)(xbl + (arow + 8) * XS + col) = pl;
        }
    }
    __syncthreads();

    // ---- Phase D: a = gelu(x @ rr_W + rr_b); y = obs_h * a -> ybh/ybl ----
    {
        const int oi0 = soiv[arow], oi1 = soiv[arow + 8];
#pragma unroll 1
        for (int jh = 0; jh < 2; jh++) {
            const int g0 = cgrp * 16 + jh * 8;
            float acc[8][4] = {};
#pragma unroll
            for (int ks = 0; ks < 4; ks++) {
                const int acol = ks * 16 + (lane & 3) * 2;
                unsigned ah0 = *(const unsigned*)(xbh + arow * XS + acol);
                unsigned ah1 = *(const unsigned*)(xbh + (arow + 8) * XS + acol);
                unsigned ah2 = *(const unsigned*)(xbh + arow * XS + acol + 8);
                unsigned ah3 = *(const unsigned*)(xbh + (arow + 8) * XS + acol + 8);
                unsigned al0 = *(const unsigned*)(xbl + arow * XS + acol);
                unsigned al1 = *(const unsigned*)(xbl + (arow + 8) * XS + acol);
                unsigned al2 = *(const unsigned*)(xbl + arow * XS + acol + 8);
                unsigned al3 = *(const unsigned*)(xbl + (arow + 8) * XS + acol + 8);
                const uint4* Wf = d_Wrf + (ks * 32 + g0) * 32 + lane;
#pragma unroll
                for (int j = 0; j < 8; j++) {
                    uint4 b = Wf[j * 32];
                    mma_bf16(acc[j], ah0, ah1, ah2, ah3, b.x, b.y);
                    mma_bf16(acc[j], al0, al1, al2, al3, b.x, b.y);
                    mma_bf16(acc[j], ah0, ah1, ah2, ah3, b.z, b.w);
                }
            }
#pragma unroll
            for (int j = 0; j < 8; j++) {
                const int col = (g0 + j) * 8 + (lane & 3) * 2;
                float2 rb = *(const float2*)(rr_b + col);
                float2 h0 = *(const float2*)(obs_embs + (long)oi0 * HID + col);
                float2 h1 = *(const float2*)(obs_embs + (long)oi1 * HID + col);
                float y00 = gelu_exact(acc[j][0] + rb.x) * h0.x;
                float y01 = gelu_exact(acc[j][1] + rb.y) * h0.y;
                float y10 = gelu_exact(acc[j][2] + rb.x) * h1.x;
                float y11 = gelu_exact(acc[j][3] + rb.y) * h1.y;
                unsigned ph, pl;
                split2(y00, y01, ph, pl);
                *(unsigned*)(ybh + arow * YS + col) = ph;
                *(unsigned*)(ybl + arow * YS + col) = pl;
                split2(y10, y11, ph, pl);
                *(unsigned*)(ybh + (arow + 8) * YS + col) = ph;
                *(unsigned*)(ybl + (arow + 8) * YS + col) = pl;
            }
        }
    }
    __syncthreads();

    // ---- Phase E: out = gelu(y @ rc_W + rc_b) ----
    {
        const long e0 = bb + arow, e1 = e0 + 8;
        const bool w0 = (e0 < (long)E), w1 = (e1 < (long)E);
#pragma unroll 1
        for (int jh = 0; jh < 2; jh++) {
            const int g0 = cgrp * 16 + jh * 8;
            float acc[8][4] = {};
#pragma unroll 1
            for (int ks = 0; ks < 16; ks++) {
                const int acol = ks * 16 + (lane & 3) * 2;
                unsigned ah0 = *(const unsigned*)(ybh + arow * YS + acol);
                unsigned ah1 = *(const unsigned*)(ybh + (arow + 8) * YS + acol);
                unsigned ah2 = *(const unsigned*)(ybh + arow * YS + acol + 8);
                unsigned ah3 = *(const unsigned*)(ybh + (arow + 8) * YS + acol + 8);
                unsigned al0 = *(const unsigned*)(ybl + arow * YS + acol);
                unsigned al1 = *(const unsigned*)(ybl + (arow + 8) * YS + acol);
                unsigned al2 = *(const unsigned*)(ybl + arow * YS + acol + 8);
                unsigned al3 = *(const unsigned*)(ybl + (arow + 8) * YS + acol + 8);
                const uint4* Wf = d_Wf + (ks * 32 + g0) * 32 + lane;
#pragma unroll
                for (int j = 0; j < 8; j++) {
                    uint4 b = Wf[j * 32];
                    mma_bf16(acc[j], ah0, ah1, ah2, ah3, b.x, b.y);
                    mma_bf16(acc[j], al0, al1, al2, al3, b.x, b.y);
                    mma_bf16(acc[j], ah0, ah1, ah2, ah3, b.z, b.w);
                }
            }
#pragma unroll
            for (int j = 0; j < 8; j++) {
                const int col = (g0 + j) * 8 + (lane & 3) * 2;
                float2 bv = *(const float2*)(rc_b + col);
                if (w0) {
                    float2 o;
                    o.x = gelu_exact(acc[j][0] + bv.x);
                    o.y = gelu_exact(acc[j][1] + bv.y);
                    *(float2*)(out + e0 * HID + col) = o;
                }
                if (w1) {
                    float2 o;
                    o.x = gelu_exact(acc[j][2] + bv.x);
                    o.y = gelu_exact(acc[j][3] + bv.y);
                    *(float2*)(out + e1 * HID + col) = o;
                }
            }
        }
    }
}

// ---------------- launch ----------------
extern "C" void kernel_launch(void* const* d_in, const int* in_sizes, int n_in,
                              void* d_out, int out_size) {
    const float* known_mask = (const float*)d_in[0];
    const int* obs_idx = (const int*)d_in[1];
    const int* obs_mask_idx = (const int*)d_in[2];
    const int* attr_idx = (const int*)d_in[3];
    const float* obs_embs = (const float*)d_in[4];
    const float* feature_emb = (const float*)d_in[5];
    const float* rm_W1 = (const float*)d_in[6];
    const float* rm_b1 = (const float*)d_in[7];
    const float* rm_W2 = (const float*)d_in[8];
    const float* rm_b2 = (const float*)d_in[9];
    const float* rr_W = (const float*)d_in[10];
    const float* rr_b = (const float*)d_in[11];
    const float* rc_W = (const float*)d_in[12];
    const float* rc_b = (const float*)d_in[13];
    int E = in_sizes[1];
    int nr = in_sizes[0] / NF;

    static bool attr_set = false;
    if (!attr_set) {
        cudaFuncSetAttribute(arn_fused, cudaFuncAttributeMaxDynamicSharedMemorySize, SMEM_SZ);
        attr_set = true;
    }

    compute_G_kernel<<<NF, NF>>>(feature_emb);
    prep_frag<0><<<64, 256>>>(rc_W, 256, 32);
    prep_frag<1><<<16, 256>>>(rm_W2, 64, 8);
    prep_frag<2><<<16, 256>>>(rr_W, 256, 32);
    prep_frag<3><<<16, 256>>>(rm_W1, 256, 32);
    prep_S<<<1, 256>>>(rm_W1);
    prep_P<<<(nr + 31) / 32, 256>>>(known_mask, nr);

    int grid = (E + MROWS - 1) / MROWS;
    arn_fused<<<grid, 256, SMEM_SZ>>>(known_mask, obs_idx, obs_mask_idx, attr_idx, obs_embs,
                                      rm_W1, rm_b1, rm_b2, rr_b, rc_b, (float*)d_out, E);
}